// round 17
// baseline (speedup 1.0000x reference)
#include <cuda_runtime.h>
#include <cuda_bf16.h>

#define BB 4
#define SS 1024
#define DD 2048
#define RPB 8                  // rows per block
#define KS 2                   // K-split factor (stage 0)
#define KH (DD / KS)           // 1024 floats per K-half
#define NBLK0 (DD / RPB * KS)  // 512 blocks (stage 0)
#define NBLK1 (DD / RPB)       // 256 blocks (fused stage 1)

// Stage-0 K-split partials (allocation-free rule: __device__ global; device refs only).
__device__ float g_vp[KS][BB][DD];

__device__ __forceinline__ float4 f4add(float4 a, float4 b) {
    return make_float4(a.x + b.x, a.y + b.y, a.z + b.z, a.w + b.w);
}

// Stage 0 (R16 shape, best measured): partial v-projection.
// Block (kc, rg): g_vp[kc][b][row] = sum_{k in half kc} cond[b][k] * Wv[row][k]
__global__ __launch_bounds__(256) void gemv0(const float* __restrict__ W,
                                             const float* __restrict__ cond) {
    __shared__ float pr[8][32];

    const int tid  = threadIdx.x;
    const int wid  = tid >> 5;
    const int lane = tid & 31;
    const int kc   = blockIdx.x & (KS - 1);
    const int rg   = blockIdx.x >> 1;
    const int r0   = rg * RPB;
    const int ka   = kc * KH + wid * 128 + lane * 4;

    float4 xa[BB];
    #pragma unroll
    for (int b = 0; b < BB; ++b)
        xa[b] = *(const float4*)(cond + b * DD + ka);

    float4 wa[8];
    #pragma unroll
    for (int r = 0; r < 8; ++r)
        wa[r] = *(const float4*)(W + (size_t)(r0 + r) * DD + ka);

    float acc[32];
    #pragma unroll
    for (int r = 0; r < 8; ++r)
        #pragma unroll
        for (int b = 0; b < BB; ++b)
            acc[r * 4 + b] = wa[r].x * xa[b].x + wa[r].y * xa[b].y +
                             wa[r].z * xa[b].z + wa[r].w * xa[b].w;

    // Butterfly: lane l ends with warp-sum for (row r0+(l>>2), batch l&3).
    int L = 32;
    #pragma unroll
    for (int m = 16; m >= 1; m >>= 1) {
        L >>= 1;
        const bool up = (lane & m) != 0;
        #pragma unroll
        for (int j = 0; j < L; ++j) {
            const float send = up ? acc[j] : acc[j + L];
            const float recv = __shfl_xor_sync(0xffffffffu, send, m);
            acc[j] = (up ? acc[j + L] : acc[j]) + recv;
        }
    }

    pr[wid][lane] = acc[0];
    __syncthreads();

    if (tid < 32) {
        float s = pr[0][tid];
        #pragma unroll
        for (int w = 1; w < 8; ++w) s += pr[w][tid];
        g_vp[kc][tid & 3][r0 + (tid >> 2)] = s;
    }
}

// Fused stage 1 + broadcast: block computes FINAL o[b][r0..r0+7]
//   o = (g_vp[0]+g_vp[1]+bv) @ Wo^T + bo     (full K per block, R13 shape)
// then broadcasts its 8 output rows to all 1024 s positions directly:
//   out[b][s][r0..r0+7] = o[b][r0..r0+7]
// 128 KB of stores per block, fire-and-forget into L2, overlapping the
// W-load stream of the other blocks.
__global__ __launch_bounds__(256) void gemv1_bcast(const float* __restrict__ W,
                                                   const float* __restrict__ bv,
                                                   const float* __restrict__ bo,
                                                   float4* __restrict__ out) {
    __shared__ float pr[8][32];
    __shared__ float fo[BB][8];    // final outputs: [batch][row offset]

    const int tid  = threadIdx.x;
    const int wid  = tid >> 5;
    const int lane = tid & 31;
    const int r0   = blockIdx.x * RPB;
    const int ka   = wid * 256 + lane * 4;
    const int kb   = ka + 128;

    // x = g_vp[0] + g_vp[1] + bv, in registers.
    const float4 ba = *(const float4*)(bv + ka);
    const float4 bb = *(const float4*)(bv + kb);
    float4 xa[BB], xb[BB];
    #pragma unroll
    for (int b = 0; b < BB; ++b) {
        xa[b] = f4add(f4add(*(const float4*)(&g_vp[0][b][ka]),
                            *(const float4*)(&g_vp[1][b][ka])), ba);
        xb[b] = f4add(f4add(*(const float4*)(&g_vp[0][b][kb]),
                            *(const float4*)(&g_vp[1][b][kb])), bb);
    }

    float4 wa[8], wb[8];
    #pragma unroll
    for (int r = 0; r < 8; ++r) {
        const float* Wr = W + (size_t)(r0 + r) * DD;
        wa[r] = *(const float4*)(Wr + ka);
        wb[r] = *(const float4*)(Wr + kb);
    }

    float acc[32];
    #pragma unroll
    for (int r = 0; r < 8; ++r)
        #pragma unroll
        for (int b = 0; b < BB; ++b)
            acc[r * 4 + b] = wa[r].x * xa[b].x + wa[r].y * xa[b].y +
                             wa[r].z * xa[b].z + wa[r].w * xa[b].w +
                             wb[r].x * xb[b].x + wb[r].y * xb[b].y +
                             wb[r].z * xb[b].z + wb[r].w * xb[b].w;

    int L = 32;
    #pragma unroll
    for (int m = 16; m >= 1; m >>= 1) {
        L >>= 1;
        const bool up = (lane & m) != 0;
        #pragma unroll
        for (int j = 0; j < L; ++j) {
            const float send = up ? acc[j] : acc[j + L];
            const float recv = __shfl_xor_sync(0xffffffffu, send, m);
            acc[j] = (up ? acc[j + L] : acc[j]) + recv;
        }
    }

    pr[wid][lane] = acc[0];
    __syncthreads();

    if (tid < 32) {
        float s = pr[0][tid];
        #pragma unroll
        for (int w = 1; w < 8; ++w) s += pr[w][tid];
        const int j = tid >> 2;            // row offset 0..7
        const int b = tid & 3;
        fo[b][j] = s + bo[r0 + j];
    }
    __syncthreads();

    // Broadcast: thread handles (b, s) pairs; 8 consecutive floats (rows
    // r0..r0+7) per pair = 2 STG.128 into one 32B sector.
    const float4* fo4 = (const float4*)fo;   // fo4[b*2], fo4[b*2+1]
    #pragma unroll
    for (int b = 0; b < BB; ++b) {
        const float4 f0 = fo4[b * 2];
        const float4 f1 = fo4[b * 2 + 1];
        #pragma unroll
        for (int ii = 0; ii < 4; ++ii) {
            const int s = tid + ii * 256;
            float4* dst = out + ((size_t)(b * SS + s) * (DD / 4)) + (r0 >> 2);
            dst[0] = f0;
            dst[1] = f1;
        }
    }
}

extern "C" void kernel_launch(void* const* d_in, const int* in_sizes, int n_in,
                              void* d_out, int out_size) {
    // Inputs: hidden_states, condition, Wq, bq, Wk, bk, Wv, bv, Wo, bo
    const float* cond = (const float*)d_in[1];
    const float* Wv   = (const float*)d_in[6];
    const float* bv   = (const float*)d_in[7];
    const float* Wo   = (const float*)d_in[8];
    const float* bo   = (const float*)d_in[9];
    float* out = (float*)d_out;

    gemv0<<<NBLK0, 256>>>(Wv, cond);
    gemv1_bcast<<<NBLK1, 256>>>(Wo, bv, bo, (float4*)out);
}